// round 1
// baseline (speedup 1.0000x reference)
#include <cuda_runtime.h>
#include <math.h>

#define Bb   2
#define Ss   2048
#define Dd   1024
#define Hh   16
#define HD   64
#define CSZ  64
#define NC   (Ss/CSZ)      // 32
#define MTOT (Bb*Ss)       // 4096
#define BH   (Bb*Hh)       // 32
#define EPSV 1e-6f

// -------- scratch (device globals; no allocation allowed) --------
__device__ float g_q[(size_t)BH * Ss * HD];      // [B,H,S,hd], phi applied
__device__ float g_k[(size_t)BH * Ss * HD];      // phi applied
__device__ float g_v[(size_t)BH * Ss * HD];
__device__ float g_attn[(size_t)MTOT * Dd];      // [B,S,D]
__device__ float g_kv[(size_t)BH * NC * HD * HD];
__device__ float g_ksum[(size_t)BH * NC * HD];

// ================= SGEMM: C = A @ W^T + bias =================
// A: [4096, 1024] row-major, W: [1024, 1024] row-major (torch Linear weight)
// mode 0: write [B,H,S,hd] layout, no activation (v)
// mode 1: write [B,H,S,hd] layout, phi = elu+1     (q, k)
// mode 2: write row-major [M, N]                    (final output)
__global__ __launch_bounds__(256) void gemm_kernel(
    const float* __restrict__ A, const float* __restrict__ W,
    const float* __restrict__ bias, float* __restrict__ Cout, int mode)
{
    __shared__ float As[8][128];
    __shared__ float Bs[8][128];
    const int tid = threadIdx.x;
    const int bm = blockIdx.y, bn = blockIdx.x;
    const int tx = tid & 15, ty = tid >> 4;
    const int lrow = tid >> 1;
    const int lcol = (tid & 1) * 4;

    const float* Aptr = A + (size_t)(bm * 128 + lrow) * Dd + lcol;
    const float* Wptr = W + (size_t)(bn * 128 + lrow) * Dd + lcol;

    float acc[8][8];
#pragma unroll
    for (int i = 0; i < 8; i++)
#pragma unroll
        for (int j = 0; j < 8; j++) acc[i][j] = 0.f;

    for (int k0 = 0; k0 < Dd; k0 += 8) {
        float4 av = *(const float4*)(Aptr + k0);
        float4 wv = *(const float4*)(Wptr + k0);
        As[lcol + 0][lrow] = av.x; As[lcol + 1][lrow] = av.y;
        As[lcol + 2][lrow] = av.z; As[lcol + 3][lrow] = av.w;
        Bs[lcol + 0][lrow] = wv.x; Bs[lcol + 1][lrow] = wv.y;
        Bs[lcol + 2][lrow] = wv.z; Bs[lcol + 3][lrow] = wv.w;
        __syncthreads();
#pragma unroll
        for (int kk = 0; kk < 8; kk++) {
            float ar[8], br[8];
#pragma unroll
            for (int i = 0; i < 8; i++) ar[i] = As[kk][ty * 8 + i];
#pragma unroll
            for (int j = 0; j < 8; j++) br[j] = Bs[kk][tx * 8 + j];
#pragma unroll
            for (int i = 0; i < 8; i++)
#pragma unroll
                for (int j = 0; j < 8; j++)
                    acc[i][j] = fmaf(ar[i], br[j], acc[i][j]);
        }
        __syncthreads();
    }

#pragma unroll
    for (int i = 0; i < 8; i++) {
        int m = bm * 128 + ty * 8 + i;
#pragma unroll
        for (int j = 0; j < 8; j++) {
            int n = bn * 128 + tx * 8 + j;
            float val = acc[i][j] + bias[n];
            if (mode == 1) val = (val > 0.f) ? (val + 1.f) : (expm1f(val) + 1.f);
            if (mode <= 1) {
                int b = m / Ss, s = m % Ss;
                int h = n / HD, e = n % HD;
                Cout[(((size_t)(b * Hh + h) * Ss + s) * HD) + e] = val;
            } else {
                Cout[(size_t)m * Dd + n] = val;
            }
        }
    }
}

// ======== per-chunk KV = k^T v  (64x64) and ksum (64) ========
__global__ __launch_bounds__(256) void chunk_kv_kernel()
{
    __shared__ float ks[CSZ * HD];
    __shared__ float vs[CSZ * HD];
    const int c = blockIdx.x, bh = blockIdx.y;
    const int tid = threadIdx.x;

    const float* kptr = g_k + ((size_t)bh * Ss + c * CSZ) * HD;
    const float* vptr = g_v + ((size_t)bh * Ss + c * CSZ) * HD;
    for (int idx = tid; idx < CSZ * HD; idx += 256) {
        ks[idx] = kptr[idx];
        vs[idx] = vptr[idx];
    }
    __syncthreads();

    const int i  = tid >> 2;        // 0..63 (k feature dim)
    const int jb = (tid & 3) * 16;  // v feature block
    float acc[16];
#pragma unroll
    for (int e = 0; e < 16; e++) acc[e] = 0.f;
    for (int s = 0; s < CSZ; s++) {
        float kv = ks[s * HD + i];
#pragma unroll
        for (int e = 0; e < 16; e++)
            acc[e] = fmaf(kv, vs[s * HD + jb + e], acc[e]);
    }
    float* out = g_kv + ((size_t)bh * NC + c) * HD * HD + i * HD + jb;
#pragma unroll
    for (int e = 0; e < 16; e++) out[e] = acc[e];

    if (tid < HD) {
        float s0 = 0.f;
        for (int s = 0; s < CSZ; s++) s0 += ks[s * HD + tid];
        g_ksum[((size_t)bh * NC + c) * HD + tid] = s0;
    }
}

// ======== exclusive prefix over chunks (in-place; step above rewrites each launch) ========
__global__ __launch_bounds__(256) void prefix_kernel()
{
    const int bh = blockIdx.x;
    const int tid = threadIdx.x;
    for (int idx = tid; idx < HD * HD; idx += 256) {
        float run = 0.f;
        for (int c = 0; c < NC; c++) {
            size_t off = ((size_t)bh * NC + c) * HD * HD + idx;
            float t = g_kv[off];
            g_kv[off] = run;
            run += t;
        }
    }
    if (tid < HD) {
        float run = 0.f;
        for (int c = 0; c < NC; c++) {
            size_t off = ((size_t)bh * NC + c) * HD + tid;
            float t = g_ksum[off];
            g_ksum[off] = run;
            run += t;
        }
    }
}

// ======== per-chunk output: inter (q @ KV_prefix) + intra (masked qk^T @ v) ========
__global__ __launch_bounds__(256) void chunk_out_kernel()
{
    extern __shared__ float sm[];
    float* qs     = sm;             // 4096
    float* kk     = sm + 4096;      // 4096
    float* vv     = sm + 8192;      // 4096
    float* ws     = sm + 12288;     // 4096 (KV_ex, then reused for A)
    float* ksum_s = sm + 16384;     // 64
    float* den_s  = ksum_s + 64;    // 64

    const int c = blockIdx.x, bh = blockIdx.y;
    const int tid = threadIdx.x;
    const size_t base = ((size_t)bh * Ss + c * CSZ) * HD;
    const float* kvex = g_kv + ((size_t)bh * NC + c) * HD * HD;

    for (int idx = tid; idx < 4096; idx += 256) {
        qs[idx] = g_q[base + idx];
        kk[idx] = g_k[base + idx];
        vv[idx] = g_v[base + idx];
        ws[idx] = kvex[idx];
    }
    if (tid < 64) ksum_s[tid] = g_ksum[((size_t)bh * NC + c) * HD + tid];
    __syncthreads();

    const int i  = tid >> 2;        // row within chunk 0..63
    const int eg = tid & 3;
    const int eb = eg * 16;         // output feature block

    float num[16];
#pragma unroll
    for (int e = 0; e < 16; e++) num[e] = 0.f;
    float den = 0.f;

    // inter-chunk: num += q[i,:] @ KV_ex[:, eb..], den += q[i,:] . ksum_ex
    for (int d = 0; d < HD; d++) {
        float qd = qs[i * HD + d];
#pragma unroll
        for (int e = 0; e < 16; e++)
            num[e] = fmaf(qd, ws[d * HD + eb + e], num[e]);
        if (eg == 0) den = fmaf(qd, ksum_s[d], den);
    }

    // A[i][j] = q[i,:] . k[j,:]  for this thread's 16 j-columns (regs only)
    float arow[16];
#pragma unroll
    for (int jj = 0; jj < 16; jj++) {
        int j = eb + jj;
        float a = 0.f;
        for (int d = 0; d < HD; d++)
            a = fmaf(qs[i * HD + d], kk[j * HD + d], a);
        arow[jj] = a;
    }
    __syncthreads();  // all inter reads of ws done
#pragma unroll
    for (int jj = 0; jj < 16; jj++) ws[i * HD + eb + jj] = arow[jj];
    __syncthreads();

    // intra-chunk causal: j <= i
    for (int j = 0; j <= i; j++) {
        float a = ws[i * HD + j];
#pragma unroll
        for (int e = 0; e < 16; e++)
            num[e] = fmaf(a, vv[j * HD + eb + e], num[e]);
        if (eg == 0) den += a;
    }
    if (eg == 0) den_s[i] = den;
    __syncthreads();

    float dinv = 1.f / (den_s[i] + EPSV);
    int b = bh >> 4, h = bh & 15;
    int sg = c * CSZ + i;
    float* outp = g_attn + ((size_t)(b * Ss + sg)) * Dd + h * HD + eb;
#pragma unroll
    for (int e = 0; e < 16; e++) outp[e] = num[e] * dinv;
}

// ================= launch =================
extern "C" void kernel_launch(void* const* d_in, const int* in_sizes, int n_in,
                              void* d_out, int out_size)
{
    const float* x  = (const float*)d_in[0];
    const float* Wq = (const float*)d_in[1];
    const float* bq = (const float*)d_in[2];
    const float* Wk = (const float*)d_in[3];
    const float* bk = (const float*)d_in[4];
    const float* Wv = (const float*)d_in[5];
    const float* bv = (const float*)d_in[6];
    const float* Wo = (const float*)d_in[7];
    const float* bo = (const float*)d_in[8];
    float* out = (float*)d_out;

    // dynamic smem for chunk_out: (4*4096 + 128) floats = 66048 B
    cudaFuncSetAttribute(chunk_out_kernel,
                         cudaFuncAttributeMaxDynamicSharedMemorySize, 67584);

    void *pq, *pk, *pv, *pattn;
    cudaGetSymbolAddress(&pq, g_q);
    cudaGetSymbolAddress(&pk, g_k);
    cudaGetSymbolAddress(&pv, g_v);
    cudaGetSymbolAddress(&pattn, g_attn);

    dim3 ggrid(Dd / 128, MTOT / 128);  // (8, 32)

    gemm_kernel<<<ggrid, 256>>>(x, Wq, bq, (float*)pq, 1);
    gemm_kernel<<<ggrid, 256>>>(x, Wk, bk, (float*)pk, 1);
    gemm_kernel<<<ggrid, 256>>>(x, Wv, bv, (float*)pv, 0);

    chunk_kv_kernel<<<dim3(NC, BH), 256>>>();
    prefix_kernel<<<BH, 256>>>();
    chunk_out_kernel<<<dim3(NC, BH), 256, 66048>>>();

    gemm_kernel<<<ggrid, 256>>>((const float*)pattn, Wo, bo, out, 2);
}

// round 2
// speedup vs baseline: 1.1279x; 1.1279x over previous
#include <cuda_runtime.h>
#include <math.h>

#define Bb   2
#define Ss   2048
#define Dd   1024
#define Hh   16
#define HD   64
#define CSZ  64
#define NC   (Ss/CSZ)      // 32
#define MTOT (Bb*Ss)       // 4096
#define BH   (Bb*Hh)       // 32
#define EPSV 1e-6f

typedef unsigned long long ull;

__device__ __forceinline__ ull pack2(float a, float b) {
    ull r; asm("mov.b64 %0,{%1,%2};" : "=l"(r) : "f"(a), "f"(b)); return r;
}
__device__ __forceinline__ void unpack2(ull v, float& a, float& b) {
    asm("mov.b64 {%0,%1},%2;" : "=f"(a), "=f"(b) : "l"(v));
}
__device__ __forceinline__ void ffma2(ull& d, ull a, ull b) {
    asm("fma.rn.f32x2 %0,%1,%2,%0;" : "+l"(d) : "l"(a), "l"(b));
}

// -------- scratch (device globals; no allocation allowed) --------
__device__ float g_q[(size_t)BH * Ss * HD];
__device__ float g_k[(size_t)BH * Ss * HD];
__device__ float g_v[(size_t)BH * Ss * HD];
__device__ float g_attn[(size_t)MTOT * Dd];
__device__ float g_kv[(size_t)BH * NC * HD * HD];
__device__ float g_ksum[(size_t)BH * NC * HD];

// ================= SGEMM body: C = A @ W^T + bias (f32x2, double-buffered) ===
// act: apply phi = elu+1.  bhsd: write [B,H,S,hd] layout else row-major [M,N].
__device__ __forceinline__ void gemm_body(
    const float* __restrict__ A, const float* __restrict__ W,
    const float* __restrict__ bias, float* __restrict__ Cout,
    int act, int bhsd, int bm, int bn)
{
    __shared__ float As[2][8][128];
    __shared__ float Bs[2][8][128];
    const int tid = threadIdx.x;
    const int tx = tid & 15, ty = tid >> 4;
    const int lrow = tid >> 1;
    const int lcol = (tid & 1) * 4;

    const float* Aptr = A + (size_t)(bm * 128 + lrow) * Dd + lcol;
    const float* Wptr = W + (size_t)(bn * 128 + lrow) * Dd + lcol;

    // prologue: load first tile
    float4 av = *(const float4*)(Aptr);
    float4 wv = *(const float4*)(Wptr);
    int buf = 0;
    As[0][lcol + 0][lrow] = av.x; As[0][lcol + 1][lrow] = av.y;
    As[0][lcol + 2][lrow] = av.z; As[0][lcol + 3][lrow] = av.w;
    Bs[0][lcol + 0][lrow] = wv.x; Bs[0][lcol + 1][lrow] = wv.y;
    Bs[0][lcol + 2][lrow] = wv.z; Bs[0][lcol + 3][lrow] = wv.w;
    __syncthreads();

    ull acc[8][4];
#pragma unroll
    for (int i = 0; i < 8; i++)
#pragma unroll
        for (int j = 0; j < 4; j++) acc[i][j] = 0ULL;

    for (int k0 = 8; k0 <= Dd; k0 += 8) {
        float4 av2, wv2;
        if (k0 < Dd) {
            av2 = *(const float4*)(Aptr + k0);
            wv2 = *(const float4*)(Wptr + k0);
        }
#pragma unroll
        for (int kk = 0; kk < 8; kk++) {
            float4 a0 = *(const float4*)&As[buf][kk][ty * 8];
            float4 a1 = *(const float4*)&As[buf][kk][ty * 8 + 4];
            ulonglong2 b0 = *(const ulonglong2*)&Bs[buf][kk][tx * 8];
            ulonglong2 b1 = *(const ulonglong2*)&Bs[buf][kk][tx * 8 + 4];
            float aa[8] = {a0.x, a0.y, a0.z, a0.w, a1.x, a1.y, a1.z, a1.w};
#pragma unroll
            for (int i = 0; i < 8; i++) {
                ull ai = pack2(aa[i], aa[i]);
                ffma2(acc[i][0], ai, b0.x);
                ffma2(acc[i][1], ai, b0.y);
                ffma2(acc[i][2], ai, b1.x);
                ffma2(acc[i][3], ai, b1.y);
            }
        }
        if (k0 < Dd) {
            buf ^= 1;
            As[buf][lcol + 0][lrow] = av2.x; As[buf][lcol + 1][lrow] = av2.y;
            As[buf][lcol + 2][lrow] = av2.z; As[buf][lcol + 3][lrow] = av2.w;
            Bs[buf][lcol + 0][lrow] = wv2.x; Bs[buf][lcol + 1][lrow] = wv2.y;
            Bs[buf][lcol + 2][lrow] = wv2.z; Bs[buf][lcol + 3][lrow] = wv2.w;
            __syncthreads();
        }
    }

    const int nbase = bn * 128 + tx * 8;
#pragma unroll
    for (int i = 0; i < 8; i++) {
        int m = bm * 128 + ty * 8 + i;
        float val[8];
#pragma unroll
        for (int j = 0; j < 4; j++) unpack2(acc[i][j], val[2 * j], val[2 * j + 1]);
#pragma unroll
        for (int jj = 0; jj < 8; jj++) {
            float v = val[jj] + bias[nbase + jj];
            if (act) v = (v > 0.f) ? (v + 1.f) : (expm1f(v) + 1.f);
            val[jj] = v;
        }
        if (bhsd) {
            int b = m / Ss, s = m % Ss;
            int h = nbase / HD, e = nbase % HD;   // nbase 8-aligned: no h crossing
            float* outp = Cout + (((size_t)(b * Hh + h) * Ss + s) * HD) + e;
            *(float4*)(outp)     = make_float4(val[0], val[1], val[2], val[3]);
            *(float4*)(outp + 4) = make_float4(val[4], val[5], val[6], val[7]);
        } else {
            float* outp = Cout + (size_t)m * Dd + nbase;
            *(float4*)(outp)     = make_float4(val[0], val[1], val[2], val[3]);
            *(float4*)(outp + 4) = make_float4(val[4], val[5], val[6], val[7]);
        }
    }
}

// fused Q/K/V projection: blockIdx.z selects weight/bias/output
__global__ __launch_bounds__(256) void gemm_qkv_kernel(
    const float* __restrict__ x,
    const float* __restrict__ Wq, const float* __restrict__ bq, float* __restrict__ Cq,
    const float* __restrict__ Wk, const float* __restrict__ bk, float* __restrict__ Ck,
    const float* __restrict__ Wv, const float* __restrict__ bv, float* __restrict__ Cv)
{
    const int z = blockIdx.z;
    const float* W = (z == 0) ? Wq : (z == 1) ? Wk : Wv;
    const float* b = (z == 0) ? bq : (z == 1) ? bk : bv;
    float* C       = (z == 0) ? Cq : (z == 1) ? Ck : Cv;
    gemm_body(x, W, b, C, (z < 2) ? 1 : 0, 1, blockIdx.y, blockIdx.x);
}

__global__ __launch_bounds__(256) void gemm_out_kernel(
    const float* __restrict__ A, const float* __restrict__ W,
    const float* __restrict__ bias, float* __restrict__ C)
{
    gemm_body(A, W, bias, C, 0, 0, blockIdx.y, blockIdx.x);
}

// ======== per-chunk KV = k^T v (64x64) and ksum (64) ========
__global__ __launch_bounds__(256) void chunk_kv_kernel()
{
    __shared__ float ks[CSZ * HD];
    __shared__ float vs[CSZ * HD];
    const int c = blockIdx.x, bh = blockIdx.y;
    const int tid = threadIdx.x;

    const float4* kp = (const float4*)(g_k + ((size_t)bh * Ss + c * CSZ) * HD);
    const float4* vp = (const float4*)(g_v + ((size_t)bh * Ss + c * CSZ) * HD);
    for (int i = tid; i < CSZ * HD / 4; i += 256) {
        ((float4*)ks)[i] = kp[i];
        ((float4*)vs)[i] = vp[i];
    }
    __syncthreads();

    const int i  = tid >> 2;        // k feature dim
    const int jb = (tid & 3) * 16;  // v feature block
    ull acc[8];
#pragma unroll
    for (int e = 0; e < 8; e++) acc[e] = 0ULL;

#pragma unroll 8
    for (int s = 0; s < CSZ; s++) {
        float kvv = ks[s * HD + i];
        ull k2 = pack2(kvv, kvv);
        const ulonglong2* vr = (const ulonglong2*)&vs[s * HD + jb];
        ulonglong2 v0 = vr[0], v1 = vr[1], v2 = vr[2], v3 = vr[3];
        ffma2(acc[0], k2, v0.x); ffma2(acc[1], k2, v0.y);
        ffma2(acc[2], k2, v1.x); ffma2(acc[3], k2, v1.y);
        ffma2(acc[4], k2, v2.x); ffma2(acc[5], k2, v2.y);
        ffma2(acc[6], k2, v3.x); ffma2(acc[7], k2, v3.y);
    }
    float buf[16];
#pragma unroll
    for (int e = 0; e < 8; e++) unpack2(acc[e], buf[2 * e], buf[2 * e + 1]);
    float* out = g_kv + ((size_t)bh * NC + c) * HD * HD + i * HD + jb;
#pragma unroll
    for (int e = 0; e < 4; e++)
        *(float4*)(out + 4 * e) = make_float4(buf[4*e], buf[4*e+1], buf[4*e+2], buf[4*e+3]);

    if (tid < HD) {
        float s0 = 0.f;
#pragma unroll 8
        for (int s = 0; s < CSZ; s++) s0 += ks[s * HD + tid];
        g_ksum[((size_t)bh * NC + c) * HD + tid] = s0;
    }
}

// ======== exclusive prefix over chunks (in-place) ========
// grid (BH, 16) x 256 threads: one [HD*HD] element per thread, scan over NC
__global__ __launch_bounds__(256) void prefix_kernel()
{
    const int bh  = blockIdx.x;
    const int idx = blockIdx.y * 256 + threadIdx.x;  // 0..4095
    float vals[NC];
#pragma unroll
    for (int c = 0; c < NC; c++)
        vals[c] = g_kv[((size_t)bh * NC + c) * HD * HD + idx];
    float run = 0.f;
#pragma unroll
    for (int c = 0; c < NC; c++) {
        g_kv[((size_t)bh * NC + c) * HD * HD + idx] = run;
        run += vals[c];
    }
    if (blockIdx.y == 0 && threadIdx.x < HD) {
        int t = threadIdx.x;
        float kvals[NC];
#pragma unroll
        for (int c = 0; c < NC; c++)
            kvals[c] = g_ksum[((size_t)bh * NC + c) * HD + t];
        float r2 = 0.f;
#pragma unroll
        for (int c = 0; c < NC; c++) {
            g_ksum[((size_t)bh * NC + c) * HD + t] = r2;
            r2 += kvals[c];
        }
    }
}

// ======== per-chunk output: inter (q @ KV_prefix) + intra (masked qk^T @ v) ====
__global__ __launch_bounds__(256) void chunk_out_kernel()
{
    extern __shared__ float sm[];
    float* qs     = sm;             // 4096
    float* kk     = sm + 4096;      // 4096
    float* vv     = sm + 8192;      // 4096
    float* ws     = sm + 12288;     // 4096 (KV_ex, then reused for A)
    float* ksum_s = sm + 16384;     // 64
    float* den_s  = ksum_s + 64;    // 64

    const int c = blockIdx.x, bh = blockIdx.y;
    const int tid = threadIdx.x;
    const size_t base = ((size_t)bh * Ss + c * CSZ) * HD;
    const float4* kvex = (const float4*)(g_kv + ((size_t)bh * NC + c) * HD * HD);

    {
        const float4* qp = (const float4*)(g_q + base);
        const float4* kp = (const float4*)(g_k + base);
        const float4* vp = (const float4*)(g_v + base);
        for (int i2 = tid; i2 < 1024; i2 += 256) {
            ((float4*)qs)[i2] = qp[i2];
            ((float4*)kk)[i2] = kp[i2];
            ((float4*)vv)[i2] = vp[i2];
            ((float4*)ws)[i2] = kvex[i2];
        }
    }
    if (tid < 64) ksum_s[tid] = g_ksum[((size_t)bh * NC + c) * HD + tid];
    __syncthreads();

    const int i  = tid >> 2;        // row within chunk 0..63
    const int eg = tid & 3;
    const int eb = eg * 16;         // output feature block

    // cache q row i in packed registers (32 x f32x2)
    ull q2[32];
    {
        const ulonglong2* qrow = (const ulonglong2*)&qs[i * HD];
#pragma unroll
        for (int t = 0; t < 16; t++) {
            ulonglong2 p = qrow[t];
            q2[2 * t] = p.x; q2[2 * t + 1] = p.y;
        }
    }

    // phase 1: arow[jj] = q[i,:] . k[eb+jj,:]  (f32x2 along reduction)
    float arow[16];
#pragma unroll
    for (int jj = 0; jj < 16; jj++) {
        ull a2 = 0ULL, b2 = 0ULL;
        const ulonglong2* krow = (const ulonglong2*)&kk[(eb + jj) * HD];
#pragma unroll
        for (int t = 0; t < 16; t++) {
            ulonglong2 p = krow[t];
            ffma2(a2, q2[2 * t], p.x);
            ffma2(b2, q2[2 * t + 1], p.y);
        }
        float xa, xb, ya, yb;
        unpack2(a2, xa, xb); unpack2(b2, ya, yb);
        arow[jj] = (xa + xb) + (ya + yb);
    }

    // phase 2: inter-chunk num/den from KV_ex (ws) and ksum
    ull num2[8];
#pragma unroll
    for (int e = 0; e < 8; e++) num2[e] = 0ULL;
    float den = 0.f;
#pragma unroll 4
    for (int t = 0; t < 32; t++) {
        float qa, qb; unpack2(q2[t], qa, qb);
        ull qa2 = pack2(qa, qa), qb2 = pack2(qb, qb);
        const ulonglong2* w0 = (const ulonglong2*)&ws[(2 * t) * HD + eb];
        const ulonglong2* w1 = (const ulonglong2*)&ws[(2 * t + 1) * HD + eb];
        ulonglong2 p0 = w0[0], p1 = w0[1], p2 = w0[2], p3 = w0[3];
        ffma2(num2[0], qa2, p0.x); ffma2(num2[1], qa2, p0.y);
        ffma2(num2[2], qa2, p1.x); ffma2(num2[3], qa2, p1.y);
        ffma2(num2[4], qa2, p2.x); ffma2(num2[5], qa2, p2.y);
        ffma2(num2[6], qa2, p3.x); ffma2(num2[7], qa2, p3.y);
        ulonglong2 r0 = w1[0], r1 = w1[1], r2 = w1[2], r3 = w1[3];
        ffma2(num2[0], qb2, r0.x); ffma2(num2[1], qb2, r0.y);
        ffma2(num2[2], qb2, r1.x); ffma2(num2[3], qb2, r1.y);
        ffma2(num2[4], qb2, r2.x); ffma2(num2[5], qb2, r2.y);
        ffma2(num2[6], qb2, r3.x); ffma2(num2[7], qb2, r3.y);
        if (eg == 0) den += qa * ksum_s[2 * t] + qb * ksum_s[2 * t + 1];
    }

    __syncthreads();  // all inter reads of ws done
#pragma unroll
    for (int e = 0; e < 4; e++)
        *(float4*)&ws[i * HD + eb + 4 * e] =
            make_float4(arow[4*e], arow[4*e+1], arow[4*e+2], arow[4*e+3]);
    __syncthreads();

    // phase 3: intra-chunk causal (j <= i)
    for (int j = 0; j <= i; j++) {
        float a = ws[i * HD + j];
        ull a2 = pack2(a, a);
        const ulonglong2* vr = (const ulonglong2*)&vv[j * HD + eb];
        ulonglong2 p0 = vr[0], p1 = vr[1], p2 = vr[2], p3 = vr[3];
        ffma2(num2[0], a2, p0.x); ffma2(num2[1], a2, p0.y);
        ffma2(num2[2], a2, p1.x); ffma2(num2[3], a2, p1.y);
        ffma2(num2[4], a2, p2.x); ffma2(num2[5], a2, p2.y);
        ffma2(num2[6], a2, p3.x); ffma2(num2[7], a2, p3.y);
        if (eg == 0) den += a;
    }
    if (eg == 0) den_s[i] = den;
    __syncthreads();

    float dinv = 1.f / (den_s[i] + EPSV);
    float buf[16];
#pragma unroll
    for (int e = 0; e < 8; e++) unpack2(num2[e], buf[2 * e], buf[2 * e + 1]);
#pragma unroll
    for (int e = 0; e < 16; e++) buf[e] *= dinv;

    int b = bh >> 4, h = bh & 15;
    int sg = c * CSZ + i;
    float* outp = g_attn + ((size_t)(b * Ss + sg)) * Dd + h * HD + eb;
#pragma unroll
    for (int e = 0; e < 4; e++)
        *(float4*)(outp + 4 * e) = make_float4(buf[4*e], buf[4*e+1], buf[4*e+2], buf[4*e+3]);
}

// ================= launch =================
extern "C" void kernel_launch(void* const* d_in, const int* in_sizes, int n_in,
                              void* d_out, int out_size)
{
    const float* x  = (const float*)d_in[0];
    const float* Wq = (const float*)d_in[1];
    const float* bq = (const float*)d_in[2];
    const float* Wk = (const float*)d_in[3];
    const float* bk = (const float*)d_in[4];
    const float* Wv = (const float*)d_in[5];
    const float* bv = (const float*)d_in[6];
    const float* Wo = (const float*)d_in[7];
    const float* bo = (const float*)d_in[8];
    float* out = (float*)d_out;

    cudaFuncSetAttribute(chunk_out_kernel,
                         cudaFuncAttributeMaxDynamicSharedMemorySize, 67584);

    void *pq, *pk, *pv, *pattn;
    cudaGetSymbolAddress(&pq, g_q);
    cudaGetSymbolAddress(&pk, g_k);
    cudaGetSymbolAddress(&pv, g_v);
    cudaGetSymbolAddress(&pattn, g_attn);

    dim3 g3(Dd / 128, MTOT / 128, 3);
    gemm_qkv_kernel<<<g3, 256>>>(x, Wq, bq, (float*)pq,
                                    Wk, bk, (float*)pk,
                                    Wv, bv, (float*)pv);

    chunk_kv_kernel<<<dim3(NC, BH), 256>>>();
    prefix_kernel<<<dim3(BH, 16), 256>>>();
    chunk_out_kernel<<<dim3(NC, BH), 256, 66048>>>();

    gemm_out_kernel<<<dim3(Dd / 128, MTOT / 128), 256>>>((const float*)pattn, Wo, bo, out);
}